// round 12
// baseline (speedup 1.0000x reference)
#include <cuda_runtime.h>
#include <math.h>
#include <stdint.h>

// ---------------------------------------------------------------------------
// BDH block: B=2, T=2048, D=512, NH=8, N=256, 3 layers.
// tf32 mma.sync m16n8k8, fp32 accumulate. 128x128 tiles, 2 CTAs/SM.
// 3-stage cp.async pipeline, one barrier per k-tile, depth-2 prefetch.
// ALL GEMMs use [n][k] B operands (pre-transposed) -> ldmatrix both sides.
// (Resubmission of R11 kernel — prior bench failed on infra, not the kernel.)
// ---------------------------------------------------------------------------

constexpr int Bb = 2, Tt = 2048, Dd = 512, NHh = 8, Nn = 256;
constexpr int BT = Bb * Tt;        // 4096
constexpr int BH = Bb * NHh;       // 16
constexpr int HN = NHh * Nn;       // 2048
constexpr float LN_EPS = 1e-5f;
constexpr float TWO_PI = 6.283185307179586f;

#define BMT 128
#define BNT 128
#define BKT 32

constexpr int RS = 36;                       // row stride in floats (pad)
constexpr int STAGE_F = 128 * RS;            // 4608 floats per stage
constexpr int NSTAGE = 3;
constexpr int SMEM_BYTES = 2 * NSTAGE * STAGE_F * 4;   // 110592 B

// Scratch (device globals: no allocation allowed)
__device__ float g_xs   [(size_t)Bb * Tt * Dd];           // full-precision residual
__device__ float g_xs_r [(size_t)Bb * Tt * Dd];           // tf32-rounded copy (A-side)
__device__ float g_xsT  [(size_t)Bb * Dd * Tt];           // transposed rounded copy (B-side)
__device__ float g_tmp  [(size_t)Bb * Tt * Dd];
__device__ float g_xsp  [(size_t)BH * Tt * Nn];           // full precision (gating only)
__device__ float g_qr   [(size_t)BH * Tt * Nn];           // rounded at write
__device__ float g_ykv  [(size_t)BH * Tt * Dd];           // LN writes rounded
__device__ float g_xy   [(size_t)Bb * Tt * NHh * Nn];     // rounded at write
__device__ float g_scores[(size_t)BH * Tt * Tt];          // rounded at write
// Pre-rounded / pre-transposed inputs ([n][k] layouts for B operands)
__device__ float g_x_r  [(size_t)Bb * Tt * Dd];           // A-side, plain
__device__ float g_winT [(size_t)Dd * Dd];                // [n][k]
__device__ float g_encT [(size_t)NHh * Nn * Dd];          // [h][n][d]
__device__ float g_encvT[(size_t)NHh * Nn * Dd];          // [h][n][d]
__device__ float g_decT [(size_t)Dd * HN];                // [d][hn]
__device__ float g_hwT  [(size_t)Dd * Dd];                // [n][k]

__device__ __forceinline__ uint32_t f2tf(float f)
{
    uint32_t u;
    asm("cvt.rna.tf32.f32 %0, %1;" : "=r"(u) : "f"(f));
    return u;
}
__device__ __forceinline__ float rndf(float f) { return __uint_as_float(f2tf(f)); }

__device__ __forceinline__ void cp16(uint32_t saddr, const void* gaddr)
{
    asm volatile("cp.async.cg.shared.global [%0], [%1], 16;" :: "r"(saddr), "l"(gaddr));
}
#define CP_COMMIT() asm volatile("cp.async.commit_group;")
#define CP_WAIT1()  asm volatile("cp.async.wait_group 1;")

__device__ __forceinline__ void ldsm_x4(uint32_t* r, uint32_t addr)
{
    asm volatile("ldmatrix.sync.aligned.m8n8.x4.shared.b16 {%0,%1,%2,%3}, [%4];"
                 : "=r"(r[0]), "=r"(r[1]), "=r"(r[2]), "=r"(r[3]) : "r"(addr));
}

// ---------------------------------------------------------------------------
// 128x128 tf32 MMA tile, B in [n][k] layout (NK). 256 threads = 8 warps in
// 2(m) x 4(n); warp tile 64x32 = 4x4 m16n8k8 frags. ldmatrix on BOTH operands.
// Inputs MUST be tf32-rounded fp32 bit patterns.
// acc[mi][nj][e]: e -> {(r,c),(r,c+1),(r+8,c),(r+8,c+1)},
//   r = lane>>2, c = (lane&3)*2 inside fragment (mi*16, nj*8).
// ---------------------------------------------------------------------------
__device__ __forceinline__ void mma_tile128_nk(
    const float* __restrict__ A, int lda,
    const float* __restrict__ Bm, int ldb,
    int kCount, float acc[4][4][4])
{
    extern __shared__ float sm[];
    float* As = sm;                           // [3][4608]
    float* Bs = sm + NSTAGE * STAGE_F;        // [3][4608]
    const int tid = threadIdx.x;
    const int lane = tid & 31, warp = tid >> 5;
    const int am = (warp >> 2) * 64, bn = (warp & 3) * 32;
    const int lrowA = (lane & 7) + 8 * ((lane >> 3) & 1);
    const int lcolA = (lane >> 4) * 4;
    const int lrowB = (lane & 7) + 8 * (lane >> 4);
    const int lcolB = ((lane >> 3) & 1) * 4;

    const uint32_t sA0 = (uint32_t)__cvta_generic_to_shared(As);
    const uint32_t sB0 = (uint32_t)__cvta_generic_to_shared(Bs);

    auto load_stage = [&](int st, int k0) {
        float* Ad = As + st * STAGE_F;
        float* Bd = Bs + st * STAGE_F;
        #pragma unroll
        for (int l = 0; l < 4; l++) {
            int c = tid + l * 256;
            int m = c >> 3, seg = (c & 7) << 2;
            cp16((uint32_t)__cvta_generic_to_shared(Ad + m * RS + seg),
                 A + (size_t)m * lda + k0 + seg);
        }
        #pragma unroll
        for (int l = 0; l < 4; l++) {
            int c = tid + l * 256;
            int n = c >> 3, seg = (c & 7) << 2;
            cp16((uint32_t)__cvta_generic_to_shared(Bd + n * RS + seg),
                 Bm + (size_t)n * ldb + k0 + seg);
        }
    };

    const int nT = kCount >> 5;
    load_stage(0, 0);
    CP_COMMIT();
    if (nT > 1) load_stage(1, BKT);
    CP_COMMIT();

    int st = 0;
    for (int t = 0; t < nT; t++) {
        CP_WAIT1();
        __syncthreads();
        if (t + 2 < nT) {
            int st2 = st + 2 - ((st + 2 >= NSTAGE) ? NSTAGE : 0);
            load_stage(st2, (t + 2) * BKT);
        }
        CP_COMMIT();

        const uint32_t aS = sA0 + st * (STAGE_F * 4);
        const uint32_t bS = sB0 + st * (STAGE_F * 4);
        #pragma unroll
        for (int kg = 0; kg < 4; kg++) {
            const int kk = kg * 8;
            uint32_t a[4][4], b[4][2];
            #pragma unroll
            for (int mi = 0; mi < 4; mi++)
                ldsm_x4(a[mi],
                        aS + (uint32_t)(((am + mi * 16 + lrowA) * RS + kk + lcolA) * 4));
            ldsm_x4(&b[0][0],
                    bS + (uint32_t)(((bn + lrowB) * RS + kk + lcolB) * 4));
            ldsm_x4(&b[2][0],
                    bS + (uint32_t)(((bn + 16 + lrowB) * RS + kk + lcolB) * 4));
            #pragma unroll
            for (int mi = 0; mi < 4; mi++)
                #pragma unroll
                for (int nj = 0; nj < 4; nj++)
                    asm volatile(
                        "mma.sync.aligned.m16n8k8.row.col.f32.tf32.tf32.f32 "
                        "{%0,%1,%2,%3}, {%4,%5,%6,%7}, {%8,%9}, {%0,%1,%2,%3};"
                        : "+f"(acc[mi][nj][0]), "+f"(acc[mi][nj][1]),
                          "+f"(acc[mi][nj][2]), "+f"(acc[mi][nj][3])
                        : "r"(a[mi][0]), "r"(a[mi][1]), "r"(a[mi][2]), "r"(a[mi][3]),
                          "r"(b[nj][0]), "r"(b[nj][1]));
        }
        st = (st + 1 == NSTAGE) ? 0 : st + 1;
    }
}

// Epilogue index helpers
#define EPI_SETUP \
    const int lane = threadIdx.x & 31, warp = threadIdx.x >> 5; \
    const int am = (warp >> 2) * 64, bn = (warp & 3) * 32; \
    const int er = lane >> 2, ec = (lane & 3) * 2;

// ---------------------------------------------------------------------------
// LN helpers
// ---------------------------------------------------------------------------
__device__ __forceinline__ void block_sum2(float& s, float& q)
{
    __shared__ float shs[8], shq[8];
    __syncthreads();
    #pragma unroll
    for (int o = 16; o > 0; o >>= 1) {
        s += __shfl_xor_sync(0xffffffffu, s, o);
        q += __shfl_xor_sync(0xffffffffu, q, o);
    }
    int w = threadIdx.x >> 5;
    if ((threadIdx.x & 31) == 0) { shs[w] = s; shq[w] = q; }
    __syncthreads();
    s = 0.f; q = 0.f;
    #pragma unroll
    for (int i = 0; i < 8; i++) { s += shs[i]; q += shq[i]; }
}

__device__ __forceinline__ void ln512_pair(float v0, float v1, float& o0, float& o1)
{
    float s = v0 + v1, q = v0 * v0 + v1 * v1;
    block_sum2(s, q);
    float mu  = s * (1.f / 512.f);
    float var = q * (1.f / 512.f) - mu * mu;
    float r   = rsqrtf(var + LN_EPS);
    o0 = (v0 - mu) * r;
    o1 = (v1 - mu) * r;
}

// ---------------------------------------------------------------------------
// Prep: round x; round+transpose all weight B-operands to [n][k].
// ---------------------------------------------------------------------------
__global__ __launch_bounds__(256) void k_prep(
    const float* __restrict__ x,   const float* __restrict__ w_in,
    const float* __restrict__ enc, const float* __restrict__ encv,
    const float* __restrict__ dec, const float* __restrict__ hw)
{
    const int stride = gridDim.x * 256;
    int i0 = blockIdx.x * 256 + threadIdx.x;
    for (int i = i0; i < Bb * Tt * Dd; i += stride) g_x_r[i] = rndf(x[i]);
    for (int i = i0; i < Dd * Dd; i += stride) {
        int n = i / Dd, k = i % Dd;
        g_winT[i] = rndf(w_in[k * Dd + n]);
        g_hwT[i]  = rndf(hw[k * Dd + n]);
    }
    for (int i = i0; i < NHh * Nn * Dd; i += stride) {
        int h = i / (Nn * Dd), r = i % (Nn * Dd);
        int n = r / Dd, d = r % Dd;
        g_encT[i]  = rndf(enc[((size_t)h * Dd + d) * Nn + n]);
        g_encvT[i] = rndf(encv[((size_t)h * Dd + d) * Nn + n]);
    }
    for (int i = i0; i < Dd * HN; i += stride) {
        int d = i / HN, hn = i % HN;
        g_decT[i] = rndf(dec[(size_t)hn * Dd + d]);
    }
}

// Tiled transpose of rounded residual: g_xs_r [b][t][d] -> g_xsT [b][d][t]
__global__ __launch_bounds__(256) void k_tr_xs()
{
    __shared__ float tile[32][33];
    int b = blockIdx.z;
    int t0 = blockIdx.x * 32, d0 = blockIdx.y * 32;
    int tx = threadIdx.x & 31, ty = threadIdx.x >> 5;   // 32 x 8
    #pragma unroll
    for (int j = 0; j < 32; j += 8)
        tile[ty + j][tx] = g_xs_r[((size_t)b * Tt + t0 + ty + j) * Dd + d0 + tx];
    __syncthreads();
    #pragma unroll
    for (int j = 0; j < 32; j += 8)
        g_xsT[((size_t)b * Dd + d0 + ty + j) * Tt + t0 + tx] = tile[tx][ty + j];
}

// ---------------------------------------------------------------------------
// Kernels
// ---------------------------------------------------------------------------

__global__ __launch_bounds__(256, 2) void k_inproj(const float* __restrict__ bias)
{
    int n0 = blockIdx.x * BNT, m0 = blockIdx.y * BMT;
    float acc[4][4][4] = {};
    mma_tile128_nk(g_x_r + (size_t)m0 * Dd, Dd, g_winT + (size_t)n0 * Dd, Dd, Dd, acc);
    EPI_SETUP;
    #pragma unroll
    for (int mi = 0; mi < 4; mi++)
        #pragma unroll
        for (int nj = 0; nj < 4; nj++) {
            int m = m0 + am + mi * 16 + er;
            int n = n0 + bn + nj * 8 + ec;
            g_tmp[(size_t)m * Dd + n]           = acc[mi][nj][0] + bias[n];
            g_tmp[(size_t)m * Dd + n + 1]       = acc[mi][nj][1] + bias[n + 1];
            g_tmp[(size_t)(m + 8) * Dd + n]     = acc[mi][nj][2] + bias[n];
            g_tmp[(size_t)(m + 8) * Dd + n + 1] = acc[mi][nj][3] + bias[n + 1];
        }
}

__global__ __launch_bounds__(256) void k_ln_inproj()
{
    size_t row = blockIdx.x;
    const float* p = g_tmp + row * 512;
    int t = threadIdx.x;
    float o0, o1;
    ln512_pair(p[t], p[t + 256], o0, o1);
    g_xs[row * 512 + t] = o0;
    g_xs[row * 512 + t + 256] = o1;
    g_xs_r[row * 512 + t] = rndf(o0);
    g_xs_r[row * 512 + t + 256] = rndf(o1);
}

// encode + relu + rope. ec even -> rope pairs.
__global__ __launch_bounds__(256, 2) void k_enc_rope()
{
    int z = blockIdx.z;
    int b = z / NHh, h = z % NHh;
    int n0 = blockIdx.x * BNT, m0 = blockIdx.y * BMT;
    const float* A  = g_xs_r + (size_t)b * Tt * Dd + (size_t)m0 * Dd;
    const float* Bm = g_encT + ((size_t)h * Nn + n0) * Dd;
    float acc[4][4][4] = {};
    mma_tile128_nk(A, Dd, Bm, Dd, Dd, acc);
    EPI_SETUP;
    #pragma unroll
    for (int mi = 0; mi < 4; mi++)
        #pragma unroll
        for (int nj = 0; nj < 4; nj++) {
            int ne = n0 + bn + nj * 8 + ec;
            float freq = exp2f((float)ne * (-1.f / 16.f)) * (1.f / TWO_PI);
            #pragma unroll
            for (int hh = 0; hh < 2; hh++) {
                int t = m0 + am + mi * 16 + er + hh * 8;
                float v0 = fmaxf(acc[mi][nj][hh * 2], 0.f);
                float v1 = fmaxf(acc[mi][nj][hh * 2 + 1], 0.f);
                float ph = (float)t * freq;
                ph = (ph - floorf(ph)) * TWO_PI;
                float sp, cp;
                sincosf(ph, &sp, &cp);
                size_t base = ((size_t)z * Tt + t) * Nn + ne;
                g_xsp[base]     = v0;
                g_xsp[base + 1] = v1;
                g_qr[base]      = rndf(v0 * cp - v1 * sp);
                g_qr[base + 1]  = rndf(v1 * cp + v0 * sp);
            }
        }
}

// scores = QR @ QR^T, strict-lower causal; rounded at write.
__global__ __launch_bounds__(256, 2) void k_qk()
{
    int stile = blockIdx.x, ttile = blockIdx.y, z = blockIdx.z;
    if (stile > ttile) return;
    const float* Q  = g_qr + ((size_t)z * Tt + (size_t)ttile * BMT) * Nn;
    const float* Kp = g_qr + ((size_t)z * Tt + (size_t)stile * BNT) * Nn;
    float acc[4][4][4] = {};
    mma_tile128_nk(Q, Nn, Kp, Nn, Nn, acc);
    EPI_SETUP;
    #pragma unroll
    for (int mi = 0; mi < 4; mi++)
        #pragma unroll
        for (int nj = 0; nj < 4; nj++) {
            int t = ttile * BMT + am + mi * 16 + er;
            int s = stile * BNT + bn + nj * 8 + ec;
            size_t r0 = ((size_t)z * Tt + t) * Tt;
            size_t r1 = ((size_t)z * Tt + t + 8) * Tt;
            g_scores[r0 + s]     = (t > s)     ? rndf(acc[mi][nj][0]) : 0.f;
            g_scores[r0 + s + 1] = (t > s + 1) ? rndf(acc[mi][nj][1]) : 0.f;
            g_scores[r1 + s]     = (t + 8 > s)     ? rndf(acc[mi][nj][2]) : 0.f;
            g_scores[r1 + s + 1] = (t + 8 > s + 1) ? rndf(acc[mi][nj][3]) : 0.f;
        }
}

// yKV = scores @ xs (causal K-extent); B = xsT [b][d][s].
__global__ __launch_bounds__(256, 2) void k_sv()
{
    int dtile = blockIdx.x, ttile = blockIdx.y, z = blockIdx.z;
    int b = z / NHh;
    const float* A  = g_scores + ((size_t)z * Tt + (size_t)ttile * BMT) * Tt;
    const float* Bm = g_xsT + ((size_t)b * Dd + dtile * BNT) * Tt;
    float acc[4][4][4] = {};
    mma_tile128_nk(A, Tt, Bm, Tt, (ttile + 1) * BMT, acc);
    EPI_SETUP;
    #pragma unroll
    for (int mi = 0; mi < 4; mi++)
        #pragma unroll
        for (int nj = 0; nj < 4; nj++) {
            int t = ttile * BMT + am + mi * 16 + er;
            int d = dtile * BNT + bn + nj * 8 + ec;
            size_t r0 = ((size_t)z * Tt + t) * Dd;
            size_t r1 = ((size_t)z * Tt + t + 8) * Dd;
            g_ykv[r0 + d]     = acc[mi][nj][0];
            g_ykv[r0 + d + 1] = acc[mi][nj][1];
            g_ykv[r1 + d]     = acc[mi][nj][2];
            g_ykv[r1 + d + 1] = acc[mi][nj][3];
        }
}

// LN of yKV, rounded at write (feeds GEMM A only).
__global__ __launch_bounds__(256) void k_ln_ykv()
{
    size_t row = blockIdx.x;
    float* p = g_ykv + row * 512;
    int t = threadIdx.x;
    float o0, o1;
    ln512_pair(p[t], p[t + 256], o0, o1);
    p[t] = rndf(o0);
    p[t + 256] = rndf(o1);
}

// y_sparse = relu(ln(yKV) @ encv[h]); xy = x_sparse * y_sparse -> [b,t,h,n].
__global__ __launch_bounds__(256, 2) void k_venc_mul()
{
    int z = blockIdx.z;
    int b = z / NHh, h = z % NHh;
    int n0 = blockIdx.x * BNT, m0 = blockIdx.y * BMT;
    const float* A  = g_ykv + (size_t)z * Tt * Dd + (size_t)m0 * Dd;
    const float* Bm = g_encvT + ((size_t)h * Nn + n0) * Dd;
    float acc[4][4][4] = {};
    mma_tile128_nk(A, Dd, Bm, Dd, Dd, acc);
    EPI_SETUP;
    #pragma unroll
    for (int mi = 0; mi < 4; mi++)
        #pragma unroll
        for (int nj = 0; nj < 4; nj++) {
            int n = n0 + bn + nj * 8 + ec;
            #pragma unroll
            for (int hh = 0; hh < 2; hh++) {
                int t = m0 + am + mi * 16 + er + hh * 8;
                size_t src = ((size_t)z * Tt + t) * Nn + n;
                size_t dst = (((size_t)(b * Tt + t)) * NHh + h) * Nn + n;
                float y0 = fmaxf(acc[mi][nj][hh * 2], 0.f);
                float y1 = fmaxf(acc[mi][nj][hh * 2 + 1], 0.f);
                g_xy[dst]     = rndf(y0 * g_xsp[src]);
                g_xy[dst + 1] = rndf(y1 * g_xsp[src + 1]);
            }
        }
}

// yMLP = xy[4096,2048] @ decoder[2048,512]; B = decT [d][hn].
__global__ __launch_bounds__(256, 2) void k_dec()
{
    int n0 = blockIdx.x * BNT, m0 = blockIdx.y * BMT;
    float acc[4][4][4] = {};
    mma_tile128_nk(g_xy + (size_t)m0 * HN, HN, g_decT + (size_t)n0 * HN, HN, HN, acc);
    EPI_SETUP;
    #pragma unroll
    for (int mi = 0; mi < 4; mi++)
        #pragma unroll
        for (int nj = 0; nj < 4; nj++) {
            int m = m0 + am + mi * 16 + er;
            int n = n0 + bn + nj * 8 + ec;
            g_tmp[(size_t)m * Dd + n]           = acc[mi][nj][0];
            g_tmp[(size_t)m * Dd + n + 1]       = acc[mi][nj][1];
            g_tmp[(size_t)(m + 8) * Dd + n]     = acc[mi][nj][2];
            g_tmp[(size_t)(m + 8) * Dd + n + 1] = acc[mi][nj][3];
        }
}

__global__ __launch_bounds__(256) void k_resid_ln()
{
    size_t row = blockIdx.x;
    const float* a = g_xs + row * 512;
    const float* bp = g_tmp + row * 512;
    int t = threadIdx.x;
    float l0, l1;
    ln512_pair(bp[t], bp[t + 256], l0, l1);
    float t0 = a[t] + l0, t1 = a[t + 256] + l1;
    float o0, o1;
    ln512_pair(t0, t1, o0, o1);
    g_xs[row * 512 + t] = o0;
    g_xs[row * 512 + t + 256] = o1;
    g_xs_r[row * 512 + t] = rndf(o0);
    g_xs_r[row * 512 + t + 256] = rndf(o1);
}

__global__ __launch_bounds__(256, 2) void k_head(
    const float* __restrict__ hb, float* __restrict__ out)
{
    int n0 = blockIdx.x * BNT, m0 = blockIdx.y * BMT;
    float acc[4][4][4] = {};
    mma_tile128_nk(g_xs_r + (size_t)m0 * Dd, Dd, g_hwT + (size_t)n0 * Dd, Dd, Dd, acc);
    EPI_SETUP;
    #pragma unroll
    for (int mi = 0; mi < 4; mi++)
        #pragma unroll
        for (int nj = 0; nj < 4; nj++) {
            int m = m0 + am + mi * 16 + er;
            int n = n0 + bn + nj * 8 + ec;
            out[(size_t)m * Dd + n]           = acc[mi][nj][0] + hb[n];
            out[(size_t)m * Dd + n + 1]       = acc[mi][nj][1] + hb[n + 1];
            out[(size_t)(m + 8) * Dd + n]     = acc[mi][nj][2] + hb[n];
            out[(size_t)(m + 8) * Dd + n + 1] = acc[mi][nj][3] + hb[n + 1];
        }
}

// ---------------------------------------------------------------------------
extern "C" void kernel_launch(void* const* d_in, const int* in_sizes, int n_in,
                              void* d_out, int out_size)
{
    const float* x    = (const float*)d_in[0];
    const float* w_in = (const float*)d_in[1];
    const float* b_in = (const float*)d_in[2];
    const float* enc  = (const float*)d_in[3];
    const float* encv = (const float*)d_in[4];
    const float* dec  = (const float*)d_in[5];
    const float* hw   = (const float*)d_in[6];
    const float* hb   = (const float*)d_in[7];
    float* out = (float*)d_out;

    static bool attr_done = false;
    if (!attr_done) {
        cudaFuncSetAttribute(k_inproj,   cudaFuncAttributeMaxDynamicSharedMemorySize, SMEM_BYTES);
        cudaFuncSetAttribute(k_enc_rope, cudaFuncAttributeMaxDynamicSharedMemorySize, SMEM_BYTES);
        cudaFuncSetAttribute(k_qk,       cudaFuncAttributeMaxDynamicSharedMemorySize, SMEM_BYTES);
        cudaFuncSetAttribute(k_sv,       cudaFuncAttributeMaxDynamicSharedMemorySize, SMEM_BYTES);
        cudaFuncSetAttribute(k_venc_mul, cudaFuncAttributeMaxDynamicSharedMemorySize, SMEM_BYTES);
        cudaFuncSetAttribute(k_dec,      cudaFuncAttributeMaxDynamicSharedMemorySize, SMEM_BYTES);
        cudaFuncSetAttribute(k_head,     cudaFuncAttributeMaxDynamicSharedMemorySize, SMEM_BYTES);
        attr_done = true;
    }

    dim3 blk(256);

    k_prep<<<512, 256>>>(x, w_in, enc, encv, dec, hw);

    k_inproj<<<dim3(Dd / BNT, BT / BMT), blk, SMEM_BYTES>>>(b_in);
    k_ln_inproj<<<BT, 256>>>();

    for (int layer = 0; layer < 3; layer++) {
        k_enc_rope<<<dim3(Nn / BNT, Tt / BMT, BH), blk, SMEM_BYTES>>>();
        k_tr_xs<<<dim3(Tt / 32, Dd / 32, Bb), 256>>>();
        k_qk<<<dim3(Tt / BNT, Tt / BMT, BH), blk, SMEM_BYTES>>>();
        k_sv<<<dim3(Dd / BNT, Tt / BMT, BH), blk, SMEM_BYTES>>>();
        k_ln_ykv<<<BH * Tt, 256>>>();
        k_venc_mul<<<dim3(Nn / BNT, Tt / BMT, BH), blk, SMEM_BYTES>>>();
        k_dec<<<dim3(Dd / BNT, BT / BMT), blk, SMEM_BYTES>>>();
        k_resid_ln<<<BT, 256>>>();
    }

    k_head<<<dim3(Dd / BNT, BT / BMT), blk, SMEM_BYTES>>>(hb, out);
}

// round 15
// speedup vs baseline: 1.2221x; 1.2221x over previous
#include <cuda_runtime.h>
#include <math.h>
#include <stdint.h>

// ---------------------------------------------------------------------------
// BDH block: B=2, T=2048, D=512, NH=8, N=256, 3 layers.
// tf32 mma.sync m16n8k8, fp32 accumulate. 128x128 tiles, 2 CTAs/SM.
// 3-stage cp.async pipeline, one barrier per k-tile, depth-2 prefetch.
// CHUNKED LINEAR ATTENTION: yKV = QR·S_prefix + (QR QR^T ⊙ mask)·xs intra-chunk.
// (Resubmission — prior bench failed on infra, not the kernel.)
// ---------------------------------------------------------------------------

constexpr int Bb = 2, Tt = 2048, Dd = 512, NHh = 8, Nn = 256;
constexpr int BT = Bb * Tt;        // 4096
constexpr int BH = Bb * NHh;       // 16
constexpr int HN = NHh * Nn;       // 2048
constexpr int NCH = 16;            // chunks of 128 along T
constexpr int CHSZ = Dd * Nn;      // 131072 floats per G/S chunk state
constexpr float LN_EPS = 1e-5f;
constexpr float TWO_PI = 6.283185307179586f;

#define BMT 128
#define BNT 128
#define BKT 32

constexpr int RS = 36;                       // row stride in floats (pad)
constexpr int STAGE_F = 128 * RS;            // 4608 floats per stage
constexpr int NSTAGE = 3;
constexpr int SMEM_BYTES = 2 * NSTAGE * STAGE_F * 4;   // 110592 B

// Scratch (device globals: no allocation allowed)
__device__ float g_xs   [(size_t)Bb * Tt * Dd];           // full-precision residual
__device__ float g_xs_r [(size_t)Bb * Tt * Dd];           // tf32-rounded copy (A-side)
__device__ float g_xsT  [(size_t)Bb * Dd * Tt];           // transposed rounded copy
__device__ float g_tmp  [(size_t)Bb * Tt * Dd];
__device__ float g_xsp  [(size_t)BH * Tt * Nn];           // full precision (gating only)
__device__ float g_qr   [(size_t)BH * Tt * Nn];           // rounded at write
__device__ float g_qrT  [(size_t)BH * Nn * Tt];           // transposed rounded copy
__device__ float g_ykv  [(size_t)BH * Tt * Dd];
__device__ float g_xy   [(size_t)Bb * Tt * NHh * Nn];
__device__ float g_G    [(size_t)BH * NCH * CHSZ];        // per-chunk states [d][n], fp32
__device__ float g_S    [(size_t)BH * NCH * CHSZ];        // exclusive prefix, tf32-rounded
__device__ float g_P    [(size_t)BH * NCH * 128 * 128];   // intra-chunk masked scores
// Pre-rounded / pre-transposed inputs ([n][k] layouts for B operands)
__device__ float g_x_r  [(size_t)Bb * Tt * Dd];
__device__ float g_winT [(size_t)Dd * Dd];
__device__ float g_encT [(size_t)NHh * Nn * Dd];
__device__ float g_encvT[(size_t)NHh * Nn * Dd];
__device__ float g_decT [(size_t)Dd * HN];
__device__ float g_hwT  [(size_t)Dd * Dd];

__device__ __forceinline__ uint32_t f2tf(float f)
{
    uint32_t u;
    asm("cvt.rna.tf32.f32 %0, %1;" : "=r"(u) : "f"(f));
    return u;
}
__device__ __forceinline__ float rndf(float f) { return __uint_as_float(f2tf(f)); }

__device__ __forceinline__ void cp16(uint32_t saddr, const void* gaddr)
{
    asm volatile("cp.async.cg.shared.global [%0], [%1], 16;" :: "r"(saddr), "l"(gaddr));
}
#define CP_COMMIT() asm volatile("cp.async.commit_group;")
#define CP_WAIT1()  asm volatile("cp.async.wait_group 1;")

__device__ __forceinline__ void ldsm_x4(uint32_t* r, uint32_t addr)
{
    asm volatile("ldmatrix.sync.aligned.m8n8.x4.shared.b16 {%0,%1,%2,%3}, [%4];"
                 : "=r"(r[0]), "=r"(r[1]), "=r"(r[2]), "=r"(r[3]) : "r"(addr));
}

// ---------------------------------------------------------------------------
// 128x128 tf32 MMA tile, B in [n][k] layout. 8 warps 2(m)x4(n); warp 64x32.
// Accumulates into acc (callable twice per kernel with a __syncthreads between).
// ---------------------------------------------------------------------------
__device__ __forceinline__ void mma_tile128_nk(
    const float* __restrict__ A, int lda,
    const float* __restrict__ Bm, int ldb,
    int kCount, float acc[4][4][4])
{
    extern __shared__ float sm[];
    float* As = sm;
    float* Bs = sm + NSTAGE * STAGE_F;
    const int tid = threadIdx.x;
    const int lane = tid & 31, warp = tid >> 5;
    const int am = (warp >> 2) * 64, bn = (warp & 3) * 32;
    const int lrowA = (lane & 7) + 8 * ((lane >> 3) & 1);
    const int lcolA = (lane >> 4) * 4;
    const int lrowB = (lane & 7) + 8 * (lane >> 4);
    const int lcolB = ((lane >> 3) & 1) * 4;

    const uint32_t sA0 = (uint32_t)__cvta_generic_to_shared(As);
    const uint32_t sB0 = (uint32_t)__cvta_generic_to_shared(Bs);

    auto load_stage = [&](int st, int k0) {
        float* Ad = As + st * STAGE_F;
        float* Bd = Bs + st * STAGE_F;
        #pragma unroll
        for (int l = 0; l < 4; l++) {
            int c = tid + l * 256;
            int m = c >> 3, seg = (c & 7) << 2;
            cp16((uint32_t)__cvta_generic_to_shared(Ad + m * RS + seg),
                 A + (size_t)m * lda + k0 + seg);
        }
        #pragma unroll
        for (int l = 0; l < 4; l++) {
            int c = tid + l * 256;
            int n = c >> 3, seg = (c & 7) << 2;
            cp16((uint32_t)__cvta_generic_to_shared(Bd + n * RS + seg),
                 Bm + (size_t)n * ldb + k0 + seg);
        }
    };

    const int nT = kCount >> 5;
    load_stage(0, 0);
    CP_COMMIT();
    if (nT > 1) load_stage(1, BKT);
    CP_COMMIT();

    int st = 0;
    for (int t = 0; t < nT; t++) {
        CP_WAIT1();
        __syncthreads();
        if (t + 2 < nT) {
            int st2 = st + 2 - ((st + 2 >= NSTAGE) ? NSTAGE : 0);
            load_stage(st2, (t + 2) * BKT);
        }
        CP_COMMIT();

        const uint32_t aS = sA0 + st * (STAGE_F * 4);
        const uint32_t bS = sB0 + st * (STAGE_F * 4);
        #pragma unroll
        for (int kg = 0; kg < 4; kg++) {
            const int kk = kg * 8;
            uint32_t a[4][4], b[4][2];
            #pragma unroll
            for (int mi = 0; mi < 4; mi++)
                ldsm_x4(a[mi],
                        aS + (uint32_t)(((am + mi * 16 + lrowA) * RS + kk + lcolA) * 4));
            ldsm_x4(&b[0][0],
                    bS + (uint32_t)(((bn + lrowB) * RS + kk + lcolB) * 4));
            ldsm_x4(&b[2][0],
                    bS + (uint32_t)(((bn + 16 + lrowB) * RS + kk + lcolB) * 4));
            #pragma unroll
            for (int mi = 0; mi < 4; mi++)
                #pragma unroll
                for (int nj = 0; nj < 4; nj++)
                    asm volatile(
                        "mma.sync.aligned.m16n8k8.row.col.f32.tf32.tf32.f32 "
                        "{%0,%1,%2,%3}, {%4,%5,%6,%7}, {%8,%9}, {%0,%1,%2,%3};"
                        : "+f"(acc[mi][nj][0]), "+f"(acc[mi][nj][1]),
                          "+f"(acc[mi][nj][2]), "+f"(acc[mi][nj][3])
                        : "r"(a[mi][0]), "r"(a[mi][1]), "r"(a[mi][2]), "r"(a[mi][3]),
                          "r"(b[nj][0]), "r"(b[nj][1]));
        }
        st = (st + 1 == NSTAGE) ? 0 : st + 1;
    }
}

// Epilogue index helpers
#define EPI_SETUP \
    const int lane = threadIdx.x & 31, warp = threadIdx.x >> 5; \
    const int am = (warp >> 2) * 64, bn = (warp & 3) * 32; \
    const int er = lane >> 2, ec = (lane & 3) * 2;

// ---------------------------------------------------------------------------
// LN helpers
// ---------------------------------------------------------------------------
__device__ __forceinline__ void block_sum2(float& s, float& q)
{
    __shared__ float shs[8], shq[8];
    __syncthreads();
    #pragma unroll
    for (int o = 16; o > 0; o >>= 1) {
        s += __shfl_xor_sync(0xffffffffu, s, o);
        q += __shfl_xor_sync(0xffffffffu, q, o);
    }
    int w = threadIdx.x >> 5;
    if ((threadIdx.x & 31) == 0) { shs[w] = s; shq[w] = q; }
    __syncthreads();
    s = 0.f; q = 0.f;
    #pragma unroll
    for (int i = 0; i < 8; i++) { s += shs[i]; q += shq[i]; }
}

__device__ __forceinline__ void ln512_pair(float v0, float v1, float& o0, float& o1)
{
    float s = v0 + v1, q = v0 * v0 + v1 * v1;
    block_sum2(s, q);
    float mu  = s * (1.f / 512.f);
    float var = q * (1.f / 512.f) - mu * mu;
    float r   = rsqrtf(var + LN_EPS);
    o0 = (v0 - mu) * r;
    o1 = (v1 - mu) * r;
}

// ---------------------------------------------------------------------------
// Prep: round x; round+transpose all weight B-operands to [n][k].
// ---------------------------------------------------------------------------
__global__ __launch_bounds__(256) void k_prep(
    const float* __restrict__ x,   const float* __restrict__ w_in,
    const float* __restrict__ enc, const float* __restrict__ encv,
    const float* __restrict__ dec, const float* __restrict__ hw)
{
    const int stride = gridDim.x * 256;
    int i0 = blockIdx.x * 256 + threadIdx.x;
    for (int i = i0; i < Bb * Tt * Dd; i += stride) g_x_r[i] = rndf(x[i]);
    for (int i = i0; i < Dd * Dd; i += stride) {
        int n = i / Dd, k = i % Dd;
        g_winT[i] = rndf(w_in[k * Dd + n]);
        g_hwT[i]  = rndf(hw[k * Dd + n]);
    }
    for (int i = i0; i < NHh * Nn * Dd; i += stride) {
        int h = i / (Nn * Dd), r = i % (Nn * Dd);
        int n = r / Dd, d = r % Dd;
        g_encT[i]  = rndf(enc[((size_t)h * Dd + d) * Nn + n]);
        g_encvT[i] = rndf(encv[((size_t)h * Dd + d) * Nn + n]);
    }
    for (int i = i0; i < Dd * HN; i += stride) {
        int d = i / HN, hn = i % HN;
        g_decT[i] = rndf(dec[(size_t)hn * Dd + d]);
    }
}

// Tiled transpose: g_xs_r [b][t][d] -> g_xsT [b][d][t]
__global__ __launch_bounds__(256) void k_tr_xs()
{
    __shared__ float tile[32][33];
    int b = blockIdx.z;
    int t0 = blockIdx.x * 32, d0 = blockIdx.y * 32;
    int tx = threadIdx.x & 31, ty = threadIdx.x >> 5;
    #pragma unroll
    for (int j = 0; j < 32; j += 8)
        tile[ty + j][tx] = g_xs_r[((size_t)b * Tt + t0 + ty + j) * Dd + d0 + tx];
    __syncthreads();
    #pragma unroll
    for (int j = 0; j < 32; j += 8)
        g_xsT[((size_t)b * Dd + d0 + ty + j) * Tt + t0 + tx] = tile[tx][ty + j];
}

// Tiled transpose: g_qr [z][t][n] -> g_qrT [z][n][t]
__global__ __launch_bounds__(256) void k_tr_qr()
{
    __shared__ float tile[32][33];
    int z = blockIdx.z;
    int t0 = blockIdx.x * 32, n0 = blockIdx.y * 32;
    int tx = threadIdx.x & 31, ty = threadIdx.x >> 5;
    #pragma unroll
    for (int j = 0; j < 32; j += 8)
        tile[ty + j][tx] = g_qr[((size_t)z * Tt + t0 + ty + j) * Nn + n0 + tx];
    __syncthreads();
    #pragma unroll
    for (int j = 0; j < 32; j += 8)
        g_qrT[((size_t)z * Nn + n0 + ty + j) * Tt + t0 + tx] = tile[tx][ty + j];
}

// ---------------------------------------------------------------------------
// Kernels
// ---------------------------------------------------------------------------

__global__ __launch_bounds__(256, 2) void k_inproj(const float* __restrict__ bias)
{
    int n0 = blockIdx.x * BNT, m0 = blockIdx.y * BMT;
    float acc[4][4][4] = {};
    mma_tile128_nk(g_x_r + (size_t)m0 * Dd, Dd, g_winT + (size_t)n0 * Dd, Dd, Dd, acc);
    EPI_SETUP;
    #pragma unroll
    for (int mi = 0; mi < 4; mi++)
        #pragma unroll
        for (int nj = 0; nj < 4; nj++) {
            int m = m0 + am + mi * 16 + er;
            int n = n0 + bn + nj * 8 + ec;
            g_tmp[(size_t)m * Dd + n]           = acc[mi][nj][0] + bias[n];
            g_tmp[(size_t)m * Dd + n + 1]       = acc[mi][nj][1] + bias[n + 1];
            g_tmp[(size_t)(m + 8) * Dd + n]     = acc[mi][nj][2] + bias[n];
            g_tmp[(size_t)(m + 8) * Dd + n + 1] = acc[mi][nj][3] + bias[n + 1];
        }
}

__global__ __launch_bounds__(256) void k_ln_inproj()
{
    size_t row = blockIdx.x;
    const float* p = g_tmp + row * 512;
    int t = threadIdx.x;
    float o0, o1;
    ln512_pair(p[t], p[t + 256], o0, o1);
    g_xs[row * 512 + t] = o0;
    g_xs[row * 512 + t + 256] = o1;
    g_xs_r[row * 512 + t] = rndf(o0);
    g_xs_r[row * 512 + t + 256] = rndf(o1);
}

// encode + relu + rope. ec even -> rope pairs.
__global__ __launch_bounds__(256, 2) void k_enc_rope()
{
    int z = blockIdx.z;
    int b = z / NHh, h = z % NHh;
    int n0 = blockIdx.x * BNT, m0 = blockIdx.y * BMT;
    const float* A  = g_xs_r + (size_t)b * Tt * Dd + (size_t)m0 * Dd;
    const float* Bm = g_encT + ((size_t)h * Nn + n0) * Dd;
    float acc[4][4][4] = {};
    mma_tile128_nk(A, Dd, Bm, Dd, Dd, acc);
    EPI_SETUP;
    #pragma unroll
    for (int mi = 0; mi < 4; mi++)
        #pragma unroll
        for (int nj = 0; nj < 4; nj++) {
            int ne = n0 + bn + nj * 8 + ec;
            float freq = exp2f((float)ne * (-1.f / 16.f)) * (1.f / TWO_PI);
            #pragma unroll
            for (int hh = 0; hh < 2; hh++) {
                int t = m0 + am + mi * 16 + er + hh * 8;
                float v0 = fmaxf(acc[mi][nj][hh * 2], 0.f);
                float v1 = fmaxf(acc[mi][nj][hh * 2 + 1], 0.f);
                float ph = (float)t * freq;
                ph = (ph - floorf(ph)) * TWO_PI;
                float sp, cp;
                sincosf(ph, &sp, &cp);
                size_t base = ((size_t)z * Tt + t) * Nn + ne;
                g_xsp[base]     = v0;
                g_xsp[base + 1] = v1;
                g_qr[base]      = rndf(v0 * cp - v1 * sp);
                g_qr[base + 1]  = rndf(v1 * cp + v0 * sp);
            }
        }
}

// Per-chunk state: G[z][j][d][n] = sum_{t in chunk j} xs[t][d] * QR[t][n]  (fp32 out)
__global__ __launch_bounds__(256, 2) void k_state()
{
    int zj = blockIdx.z;                 // z*NCH + j
    int z = zj / NCH, j = zj % NCH;
    int b = z / NHh;
    int n0 = blockIdx.x * BNT;           // n-tile (0..1)
    int m0 = blockIdx.y * BMT;           // d-tile (0..3)
    const float* A  = g_xsT + ((size_t)b * Dd + m0) * Tt + j * 128;   // [d][t]
    const float* Bm = g_qrT + ((size_t)z * Nn + n0) * Tt + j * 128;   // [n][t]
    float acc[4][4][4] = {};
    mma_tile128_nk(A, Tt, Bm, Tt, 128, acc);
    EPI_SETUP;
    float* G = g_G + (size_t)zj * CHSZ;
    #pragma unroll
    for (int mi = 0; mi < 4; mi++)
        #pragma unroll
        for (int nj = 0; nj < 4; nj++) {
            int d = m0 + am + mi * 16 + er;
            int n = n0 + bn + nj * 8 + ec;
            G[(size_t)d * Nn + n]           = acc[mi][nj][0];
            G[(size_t)d * Nn + n + 1]       = acc[mi][nj][1];
            G[(size_t)(d + 8) * Nn + n]     = acc[mi][nj][2];
            G[(size_t)(d + 8) * Nn + n + 1] = acc[mi][nj][3];
        }
}

// Exclusive prefix over chunks: S[z][j] = rndf( sum_{j'<j} G[z][j'] )
__global__ __launch_bounds__(256) void k_scan()
{
    int z = blockIdx.y;
    int e = blockIdx.x * 256 + threadIdx.x;        // 0..CHSZ-1
    float run = 0.f;
    size_t base = (size_t)z * NCH * CHSZ + e;
    #pragma unroll
    for (int j = 0; j < NCH; j++) {
        g_S[base + (size_t)j * CHSZ] = rndf(run);
        run += g_G[base + (size_t)j * CHSZ];
    }
}

// Intra-chunk masked scores: P[z][i] = (QR_i QR_i^T) ⊙ strict-lower, rounded.
__global__ __launch_bounds__(256, 2) void k_qk_intra()
{
    int zi = blockIdx.x;
    int z = zi / NCH, i = zi % NCH;
    const float* Q = g_qr + ((size_t)z * Tt + (size_t)i * 128) * Nn;
    float acc[4][4][4] = {};
    mma_tile128_nk(Q, Nn, Q, Nn, Nn, acc);
    EPI_SETUP;
    float* P = g_P + (size_t)zi * 128 * 128;
    #pragma unroll
    for (int mi = 0; mi < 4; mi++)
        #pragma unroll
        for (int nj = 0; nj < 4; nj++) {
            int t = am + mi * 16 + er;          // local row
            int s = bn + nj * 8 + ec;           // local col
            P[(size_t)t * 128 + s]           = (t > s)     ? rndf(acc[mi][nj][0]) : 0.f;
            P[(size_t)t * 128 + s + 1]       = (t > s + 1) ? rndf(acc[mi][nj][1]) : 0.f;
            P[(size_t)(t + 8) * 128 + s]     = (t + 8 > s)     ? rndf(acc[mi][nj][2]) : 0.f;
            P[(size_t)(t + 8) * 128 + s + 1] = (t + 8 > s + 1) ? rndf(acc[mi][nj][3]) : 0.f;
        }
}

// yKV chunk: inter (QR_i · S_i, K=256) + intra (P_i · xs_i, K=128).
__global__ __launch_bounds__(256, 2) void k_attn()
{
    int dtile = blockIdx.x;              // 0..3
    int i = blockIdx.y;                  // chunk
    int z = blockIdx.z;
    int b = z / NHh;
    float acc[4][4][4] = {};
    // inter: A = QR_i [t][n] (K=256), B = S[z][i] [d][n] rows d
    const float* A1 = g_qr + ((size_t)z * Tt + (size_t)i * 128) * Nn;
    const float* B1 = g_S + ((size_t)(z * NCH + i)) * CHSZ + (size_t)(dtile * 128) * Nn;
    mma_tile128_nk(A1, Nn, B1, Nn, Nn, acc);
    __syncthreads();
    // intra: A = P[z][i] [t][s] (K=128), B = xsT [d][t-in-chunk]
    const float* A2 = g_P + (size_t)(z * NCH + i) * 128 * 128;
    const float* B2 = g_xsT + ((size_t)b * Dd + dtile * 128) * Tt + i * 128;
    mma_tile128_nk(A2, 128, B2, Tt, 128, acc);
    EPI_SETUP;
    #pragma unroll
    for (int mi = 0; mi < 4; mi++)
        #pragma unroll
        for (int nj = 0; nj < 4; nj++) {
            int t = i * 128 + am + mi * 16 + er;
            int d = dtile * 128 + bn + nj * 8 + ec;
            size_t r0 = ((size_t)z * Tt + t) * Dd;
            size_t r1 = ((size_t)z * Tt + t + 8) * Dd;
            g_ykv[r0 + d]     = acc[mi][nj][0];
            g_ykv[r0 + d + 1] = acc[mi][nj][1];
            g_ykv[r1 + d]     = acc[mi][nj][2];
            g_ykv[r1 + d + 1] = acc[mi][nj][3];
        }
}

// LN of yKV, rounded at write.
__global__ __launch_bounds__(256) void k_ln_ykv()
{
    size_t row = blockIdx.x;
    float* p = g_ykv + row * 512;
    int t = threadIdx.x;
    float o0, o1;
    ln512_pair(p[t], p[t + 256], o0, o1);
    p[t] = rndf(o0);
    p[t + 256] = rndf(o1);
}

// y_sparse = relu(ln(yKV) @ encv[h]); xy = x_sparse * y_sparse -> [b,t,h,n].
__global__ __launch_bounds__(256, 2) void k_venc_mul()
{
    int z = blockIdx.z;
    int b = z / NHh, h = z % NHh;
    int n0 = blockIdx.x * BNT, m0 = blockIdx.y * BMT;
    const float* A  = g_ykv + (size_t)z * Tt * Dd + (size_t)m0 * Dd;
    const float* Bm = g_encvT + ((size_t)h * Nn + n0) * Dd;
    float acc[4][4][4] = {};
    mma_tile128_nk(A, Dd, Bm, Dd, Dd, acc);
    EPI_SETUP;
    #pragma unroll
    for (int mi = 0; mi < 4; mi++)
        #pragma unroll
        for (int nj = 0; nj < 4; nj++) {
            int n = n0 + bn + nj * 8 + ec;
            #pragma unroll
            for (int hh = 0; hh < 2; hh++) {
                int t = m0 + am + mi * 16 + er + hh * 8;
                size_t src = ((size_t)z * Tt + t) * Nn + n;
                size_t dst = (((size_t)(b * Tt + t)) * NHh + h) * Nn + n;
                float y0 = fmaxf(acc[mi][nj][hh * 2], 0.f);
                float y1 = fmaxf(acc[mi][nj][hh * 2 + 1], 0.f);
                g_xy[dst]     = rndf(y0 * g_xsp[src]);
                g_xy[dst + 1] = rndf(y1 * g_xsp[src + 1]);
            }
        }
}

// yMLP = xy[4096,2048] @ decoder[2048,512]; B = decT [d][hn].
__global__ __launch_bounds__(256, 2) void k_dec()
{
    int n0 = blockIdx.x * BNT, m0 = blockIdx.y * BMT;
    float acc[4][4][4] = {};
    mma_tile128_nk(g_xy + (size_t)m0 * HN, HN, g_decT + (size_t)n0 * HN, HN, HN, acc);
    EPI_SETUP;
    #pragma unroll
    for (int mi = 0; mi < 4; mi++)
        #pragma unroll
        for (int nj = 0; nj < 4; nj++) {
            int m = m0 + am + mi * 16 + er;
            int n = n0 + bn + nj * 8 + ec;
            g_tmp[(size_t)m * Dd + n]           = acc[mi][nj][0];
            g_tmp[(size_t)m * Dd + n + 1]       = acc[mi][nj][1];
            g_tmp[(size_t)(m + 8) * Dd + n]     = acc[mi][nj][2];
            g_tmp[(size_t)(m + 8) * Dd + n + 1] = acc[mi][nj][3];
        }
}

__global__ __launch_bounds__(256) void k_resid_ln()
{
    size_t row = blockIdx.x;
    const float* a = g_xs + row * 512;
    const float* bp = g_tmp + row * 512;
    int t = threadIdx.x;
    float l0, l1;
    ln512_pair(bp[t], bp[t + 256], l0, l1);
    float t0 = a[t] + l0, t1 = a[t + 256] + l1;
    float o0, o1;
    ln512_pair(t0, t1, o0, o1);
    g_xs[row * 512 + t] = o0;
    g_xs[row * 512 + t + 256] = o1;
    g_xs_r[row * 512 + t] = rndf(o0);
    g_xs_r[row * 512 + t + 256] = rndf(o1);
}

__global__ __launch_bounds__(256, 2) void k_head(
    const float* __restrict__ hb, float* __restrict__ out)
{
    int n0 = blockIdx.x * BNT, m0 = blockIdx.y * BMT;
    float acc[4][4][4] = {};
    mma_tile128_nk(g_xs_r + (size_t)m0 * Dd, Dd, g_hwT + (size_t)n0 * Dd, Dd, Dd, acc);
    EPI_SETUP;
    #pragma unroll
    for (int mi = 0; mi < 4; mi++)
        #pragma unroll
        for (int nj = 0; nj < 4; nj++) {
            int m = m0 + am + mi * 16 + er;
            int n = n0 + bn + nj * 8 + ec;
            out[(size_t)m * Dd + n]           = acc[mi][nj][0] + hb[n];
            out[(size_t)m * Dd + n + 1]       = acc[mi][nj][1] + hb[n + 1];
            out[(size_t)(m + 8) * Dd + n]     = acc[mi][nj][2] + hb[n];
            out[(size_t)(m + 8) * Dd + n + 1] = acc[mi][nj][3] + hb[n + 1];
        }
}

// ---------------------------------------------------------------------------
extern "C" void kernel_launch(void* const* d_in, const int* in_sizes, int n_in,
                              void* d_out, int out_size)
{
    const float* x    = (const float*)d_in[0];
    const float* w_in = (const float*)d_in[1];
    const float* b_in = (const float*)d_in[2];
    const float* enc  = (const float*)d_in[3];
    const float* encv = (const float*)d_in[4];
    const float* dec  = (const float*)d_in[5];
    const float* hw   = (const float*)d_in[6];
    const float* hb   = (const float*)d_in[7];
    float* out = (float*)d_out;

    static bool attr_done = false;
    if (!attr_done) {
        cudaFuncSetAttribute(k_inproj,   cudaFuncAttributeMaxDynamicSharedMemorySize, SMEM_BYTES);
        cudaFuncSetAttribute(k_enc_rope, cudaFuncAttributeMaxDynamicSharedMemorySize, SMEM_BYTES);
        cudaFuncSetAttribute(k_state,    cudaFuncAttributeMaxDynamicSharedMemorySize, SMEM_BYTES);
        cudaFuncSetAttribute(k_qk_intra, cudaFuncAttributeMaxDynamicSharedMemorySize, SMEM_BYTES);
        cudaFuncSetAttribute(k_attn,     cudaFuncAttributeMaxDynamicSharedMemorySize, SMEM_BYTES);
        cudaFuncSetAttribute(k_venc_mul, cudaFuncAttributeMaxDynamicSharedMemorySize, SMEM_BYTES);
        cudaFuncSetAttribute(k_dec,      cudaFuncAttributeMaxDynamicSharedMemorySize, SMEM_BYTES);
        cudaFuncSetAttribute(k_head,     cudaFuncAttributeMaxDynamicSharedMemorySize, SMEM_BYTES);
        attr_done = true;
    }

    dim3 blk(256);

    k_prep<<<512, 256>>>(x, w_in, enc, encv, dec, hw);

    k_inproj<<<dim3(Dd / BNT, BT / BMT), blk, SMEM_BYTES>>>(b_in);
    k_ln_inproj<<<BT, 256>>>();

    for (int layer = 0; layer < 3; layer++) {
        k_enc_rope<<<dim3(Nn / BNT, Tt / BMT, BH), blk, SMEM_BYTES>>>();
        k_tr_xs<<<dim3(Tt / 32, Dd / 32, Bb), 256>>>();
        k_tr_qr<<<dim3(Tt / 32, Nn / 32, BH), 256>>>();
        k_state<<<dim3(Nn / BNT, Dd / BMT, BH * NCH), blk, SMEM_BYTES>>>();
        k_scan<<<dim3(CHSZ / 256, BH), 256>>>();
        k_qk_intra<<<dim3(BH * NCH), blk, SMEM_BYTES>>>();
        k_attn<<<dim3(Dd / BNT, NCH, BH), blk, SMEM_BYTES>>>();
        k_ln_ykv<<<BH * Tt, 256>>>();
        k_venc_mul<<<dim3(Nn / BNT, Tt / BMT, BH), blk, SMEM_BYTES>>>();
        k_dec<<<dim3(Dd / BNT, BT / BMT), blk, SMEM_BYTES>>>();
        k_resid_ln<<<BT, 256>>>();
    }

    k_head<<<dim3(Dd / BNT, BT / BMT), blk, SMEM_BYTES>>>(hb, out);
}

// round 17
// speedup vs baseline: 1.2694x; 1.0388x over previous
#include <cuda_runtime.h>
#include <math.h>
#include <stdint.h>

// ---------------------------------------------------------------------------
// BDH block: B=2, T=2048, D=512, NH=8, N=256, 3 layers.
// tf32 mma.sync m16n8k8, fp32 accumulate. 128x128 tiles, 2 CTAs/SM.
// 3-stage cp.async pipeline, one barrier per k-tile, depth-2 prefetch.
// CHUNKED LINEAR ATTENTION with FUSED state+scan: one K=2048 MMA sweep per
// (d,n) tile dumps the exclusive prefix S[j] from the accumulator every
// 4 k-tiles (chunk = 128 = 4 x BKT). G never materializes.
// ---------------------------------------------------------------------------

constexpr int Bb = 2, Tt = 2048, Dd = 512, NHh = 8, Nn = 256;
constexpr int BT = Bb * Tt;        // 4096
constexpr int BH = Bb * NHh;       // 16
constexpr int HN = NHh * Nn;       // 2048
constexpr int NCH = 16;            // chunks of 128 along T
constexpr int CHSZ = Dd * Nn;      // 131072 floats per S chunk state
constexpr float LN_EPS = 1e-5f;
constexpr float TWO_PI = 6.283185307179586f;

#define BMT 128
#define BNT 128
#define BKT 32

constexpr int RS = 36;                       // row stride in floats (pad)
constexpr int STAGE_F = 128 * RS;            // 4608 floats per stage
constexpr int NSTAGE = 3;
constexpr int SMEM_BYTES = 2 * NSTAGE * STAGE_F * 4;   // 110592 B
constexpr int SS_B_STAGE = 64 * RS;          // 2304 floats per B stage (state_scan)
constexpr int SMEM_SS = NSTAGE * (STAGE_F + SS_B_STAGE) * 4;   // 82944 B

// Scratch (device globals: no allocation allowed)
__device__ float g_xs   [(size_t)Bb * Tt * Dd];           // full-precision residual
__device__ float g_xs_r [(size_t)Bb * Tt * Dd];           // tf32-rounded copy (A-side)
__device__ float g_xsT  [(size_t)Bb * Dd * Tt];           // transposed rounded copy
__device__ float g_tmp  [(size_t)Bb * Tt * Dd];
__device__ float g_xsp  [(size_t)BH * Tt * Nn];           // full precision (gating only)
__device__ float g_qr   [(size_t)BH * Tt * Nn];           // rounded at write
__device__ float g_qrT  [(size_t)BH * Nn * Tt];           // transposed rounded copy
__device__ float g_ykv  [(size_t)BH * Tt * Dd];
__device__ float g_xy   [(size_t)Bb * Tt * NHh * Nn];
__device__ float g_S    [(size_t)BH * NCH * CHSZ];        // exclusive prefix, tf32-rounded
__device__ float g_P    [(size_t)BH * NCH * 128 * 128];   // intra-chunk masked scores
// Pre-rounded / pre-transposed inputs ([n][k] layouts for B operands)
__device__ float g_x_r  [(size_t)Bb * Tt * Dd];
__device__ float g_winT [(size_t)Dd * Dd];
__device__ float g_encT [(size_t)NHh * Nn * Dd];
__device__ float g_encvT[(size_t)NHh * Nn * Dd];
__device__ float g_decT [(size_t)Dd * HN];
__device__ float g_hwT  [(size_t)Dd * Dd];

__device__ __forceinline__ uint32_t f2tf(float f)
{
    uint32_t u;
    asm("cvt.rna.tf32.f32 %0, %1;" : "=r"(u) : "f"(f));
    return u;
}
__device__ __forceinline__ float rndf(float f) { return __uint_as_float(f2tf(f)); }

__device__ __forceinline__ void cp16(uint32_t saddr, const void* gaddr)
{
    asm volatile("cp.async.cg.shared.global [%0], [%1], 16;" :: "r"(saddr), "l"(gaddr));
}
#define CP_COMMIT() asm volatile("cp.async.commit_group;")
#define CP_WAIT1()  asm volatile("cp.async.wait_group 1;")

__device__ __forceinline__ void ldsm_x4(uint32_t* r, uint32_t addr)
{
    asm volatile("ldmatrix.sync.aligned.m8n8.x4.shared.b16 {%0,%1,%2,%3}, [%4];"
                 : "=r"(r[0]), "=r"(r[1]), "=r"(r[2]), "=r"(r[3]) : "r"(addr));
}

// ---------------------------------------------------------------------------
// 128x128 tf32 MMA tile, B in [n][k] layout. 8 warps 2(m)x4(n); warp 64x32.
// Accumulates into acc (callable twice per kernel; barrier-safe).
// ---------------------------------------------------------------------------
__device__ __forceinline__ void mma_tile128_nk(
    const float* __restrict__ A, int lda,
    const float* __restrict__ Bm, int ldb,
    int kCount, float acc[4][4][4])
{
    extern __shared__ float sm[];
    float* As = sm;
    float* Bs = sm + NSTAGE * STAGE_F;
    const int tid = threadIdx.x;
    const int lane = tid & 31, warp = tid >> 5;
    const int am = (warp >> 2) * 64, bn = (warp & 3) * 32;
    const int lrowA = (lane & 7) + 8 * ((lane >> 3) & 1);
    const int lcolA = (lane >> 4) * 4;
    const int lrowB = (lane & 7) + 8 * (lane >> 4);
    const int lcolB = ((lane >> 3) & 1) * 4;

    const uint32_t sA0 = (uint32_t)__cvta_generic_to_shared(As);
    const uint32_t sB0 = (uint32_t)__cvta_generic_to_shared(Bs);

    auto load_stage = [&](int st, int k0) {
        float* Ad = As + st * STAGE_F;
        float* Bd = Bs + st * STAGE_F;
        #pragma unroll
        for (int l = 0; l < 4; l++) {
            int c = tid + l * 256;
            int m = c >> 3, seg = (c & 7) << 2;
            cp16((uint32_t)__cvta_generic_to_shared(Ad + m * RS + seg),
                 A + (size_t)m * lda + k0 + seg);
        }
        #pragma unroll
        for (int l = 0; l < 4; l++) {
            int c = tid + l * 256;
            int n = c >> 3, seg = (c & 7) << 2;
            cp16((uint32_t)__cvta_generic_to_shared(Bd + n * RS + seg),
                 Bm + (size_t)n * ldb + k0 + seg);
        }
    };

    const int nT = kCount >> 5;
    load_stage(0, 0);
    CP_COMMIT();
    if (nT > 1) load_stage(1, BKT);
    CP_COMMIT();

    int st = 0;
    for (int t = 0; t < nT; t++) {
        CP_WAIT1();
        __syncthreads();
        if (t + 2 < nT) {
            int st2 = st + 2 - ((st + 2 >= NSTAGE) ? NSTAGE : 0);
            load_stage(st2, (t + 2) * BKT);
        }
        CP_COMMIT();

        const uint32_t aS = sA0 + st * (STAGE_F * 4);
        const uint32_t bS = sB0 + st * (STAGE_F * 4);
        #pragma unroll
        for (int kg = 0; kg < 4; kg++) {
            const int kk = kg * 8;
            uint32_t a[4][4], b[4][2];
            #pragma unroll
            for (int mi = 0; mi < 4; mi++)
                ldsm_x4(a[mi],
                        aS + (uint32_t)(((am + mi * 16 + lrowA) * RS + kk + lcolA) * 4));
            ldsm_x4(&b[0][0],
                    bS + (uint32_t)(((bn + lrowB) * RS + kk + lcolB) * 4));
            ldsm_x4(&b[2][0],
                    bS + (uint32_t)(((bn + 16 + lrowB) * RS + kk + lcolB) * 4));
            #pragma unroll
            for (int mi = 0; mi < 4; mi++)
                #pragma unroll
                for (int nj = 0; nj < 4; nj++)
                    asm volatile(
                        "mma.sync.aligned.m16n8k8.row.col.f32.tf32.tf32.f32 "
                        "{%0,%1,%2,%3}, {%4,%5,%6,%7}, {%8,%9}, {%0,%1,%2,%3};"
                        : "+f"(acc[mi][nj][0]), "+f"(acc[mi][nj][1]),
                          "+f"(acc[mi][nj][2]), "+f"(acc[mi][nj][3])
                        : "r"(a[mi][0]), "r"(a[mi][1]), "r"(a[mi][2]), "r"(a[mi][3]),
                          "r"(b[nj][0]), "r"(b[nj][1]));
        }
        st = (st + 1 == NSTAGE) ? 0 : st + 1;
    }
}

// Epilogue index helpers
#define EPI_SETUP \
    const int lane = threadIdx.x & 31, warp = threadIdx.x >> 5; \
    const int am = (warp >> 2) * 64, bn = (warp & 3) * 32; \
    const int er = lane >> 2, ec = (lane & 3) * 2;

// ---------------------------------------------------------------------------
// LN helpers
// ---------------------------------------------------------------------------
__device__ __forceinline__ void block_sum2(float& s, float& q)
{
    __shared__ float shs[8], shq[8];
    __syncthreads();
    #pragma unroll
    for (int o = 16; o > 0; o >>= 1) {
        s += __shfl_xor_sync(0xffffffffu, s, o);
        q += __shfl_xor_sync(0xffffffffu, q, o);
    }
    int w = threadIdx.x >> 5;
    if ((threadIdx.x & 31) == 0) { shs[w] = s; shq[w] = q; }
    __syncthreads();
    s = 0.f; q = 0.f;
    #pragma unroll
    for (int i = 0; i < 8; i++) { s += shs[i]; q += shq[i]; }
}

__device__ __forceinline__ void ln512_pair(float v0, float v1, float& o0, float& o1)
{
    float s = v0 + v1, q = v0 * v0 + v1 * v1;
    block_sum2(s, q);
    float mu  = s * (1.f / 512.f);
    float var = q * (1.f / 512.f) - mu * mu;
    float r   = rsqrtf(var + LN_EPS);
    o0 = (v0 - mu) * r;
    o1 = (v1 - mu) * r;
}

// ---------------------------------------------------------------------------
// Prep: round x; round+transpose all weight B-operands to [n][k].
// ---------------------------------------------------------------------------
__global__ __launch_bounds__(256) void k_prep(
    const float* __restrict__ x,   const float* __restrict__ w_in,
    const float* __restrict__ enc, const float* __restrict__ encv,
    const float* __restrict__ dec, const float* __restrict__ hw)
{
    const int stride = gridDim.x * 256;
    int i0 = blockIdx.x * 256 + threadIdx.x;
    for (int i = i0; i < Bb * Tt * Dd; i += stride) g_x_r[i] = rndf(x[i]);
    for (int i = i0; i < Dd * Dd; i += stride) {
        int n = i / Dd, k = i % Dd;
        g_winT[i] = rndf(w_in[k * Dd + n]);
        g_hwT[i]  = rndf(hw[k * Dd + n]);
    }
    for (int i = i0; i < NHh * Nn * Dd; i += stride) {
        int h = i / (Nn * Dd), r = i % (Nn * Dd);
        int n = r / Dd, d = r % Dd;
        g_encT[i]  = rndf(enc[((size_t)h * Dd + d) * Nn + n]);
        g_encvT[i] = rndf(encv[((size_t)h * Dd + d) * Nn + n]);
    }
    for (int i = i0; i < Dd * HN; i += stride) {
        int d = i / HN, hn = i % HN;
        g_decT[i] = rndf(dec[(size_t)hn * Dd + d]);
    }
}

// Tiled transpose: g_xs_r [b][t][d] -> g_xsT [b][d][t]
__global__ __launch_bounds__(256) void k_tr_xs()
{
    __shared__ float tile[32][33];
    int b = blockIdx.z;
    int t0 = blockIdx.x * 32, d0 = blockIdx.y * 32;
    int tx = threadIdx.x & 31, ty = threadIdx.x >> 5;
    #pragma unroll
    for (int j = 0; j < 32; j += 8)
        tile[ty + j][tx] = g_xs_r[((size_t)b * Tt + t0 + ty + j) * Dd + d0 + tx];
    __syncthreads();
    #pragma unroll
    for (int j = 0; j < 32; j += 8)
        g_xsT[((size_t)b * Dd + d0 + ty + j) * Tt + t0 + tx] = tile[tx][ty + j];
}

// Tiled transpose: g_qr [z][t][n] -> g_qrT [z][n][t]
__global__ __launch_bounds__(256) void k_tr_qr()
{
    __shared__ float tile[32][33];
    int z = blockIdx.z;
    int t0 = blockIdx.x * 32, n0 = blockIdx.y * 32;
    int tx = threadIdx.x & 31, ty = threadIdx.x >> 5;
    #pragma unroll
    for (int j = 0; j < 32; j += 8)
        tile[ty + j][tx] = g_qr[((size_t)z * Tt + t0 + ty + j) * Nn + n0 + tx];
    __syncthreads();
    #pragma unroll
    for (int j = 0; j < 32; j += 8)
        g_qrT[((size_t)z * Nn + n0 + ty + j) * Tt + t0 + tx] = tile[tx][ty + j];
}

// ---------------------------------------------------------------------------
// Kernels
// ---------------------------------------------------------------------------

__global__ __launch_bounds__(256, 2) void k_inproj(const float* __restrict__ bias)
{
    int n0 = blockIdx.x * BNT, m0 = blockIdx.y * BMT;
    float acc[4][4][4] = {};
    mma_tile128_nk(g_x_r + (size_t)m0 * Dd, Dd, g_winT + (size_t)n0 * Dd, Dd, Dd, acc);
    EPI_SETUP;
    #pragma unroll
    for (int mi = 0; mi < 4; mi++)
        #pragma unroll
        for (int nj = 0; nj < 4; nj++) {
            int m = m0 + am + mi * 16 + er;
            int n = n0 + bn + nj * 8 + ec;
            g_tmp[(size_t)m * Dd + n]           = acc[mi][nj][0] + bias[n];
            g_tmp[(size_t)m * Dd + n + 1]       = acc[mi][nj][1] + bias[n + 1];
            g_tmp[(size_t)(m + 8) * Dd + n]     = acc[mi][nj][2] + bias[n];
            g_tmp[(size_t)(m + 8) * Dd + n + 1] = acc[mi][nj][3] + bias[n + 1];
        }
}

__global__ __launch_bounds__(256) void k_ln_inproj()
{
    size_t row = blockIdx.x;
    const float* p = g_tmp + row * 512;
    int t = threadIdx.x;
    float o0, o1;
    ln512_pair(p[t], p[t + 256], o0, o1);
    g_xs[row * 512 + t] = o0;
    g_xs[row * 512 + t + 256] = o1;
    g_xs_r[row * 512 + t] = rndf(o0);
    g_xs_r[row * 512 + t + 256] = rndf(o1);
}

// encode + relu + rope. ec even -> rope pairs.
__global__ __launch_bounds__(256, 2) void k_enc_rope()
{
    int z = blockIdx.z;
    int b = z / NHh, h = z % NHh;
    int n0 = blockIdx.x * BNT, m0 = blockIdx.y * BMT;
    const float* A  = g_xs_r + (size_t)b * Tt * Dd + (size_t)m0 * Dd;
    const float* Bm = g_encT + ((size_t)h * Nn + n0) * Dd;
    float acc[4][4][4] = {};
    mma_tile128_nk(A, Dd, Bm, Dd, Dd, acc);
    EPI_SETUP;
    #pragma unroll
    for (int mi = 0; mi < 4; mi++)
        #pragma unroll
        for (int nj = 0; nj < 4; nj++) {
            int ne = n0 + bn + nj * 8 + ec;
            float freq = exp2f((float)ne * (-1.f / 16.f)) * (1.f / TWO_PI);
            #pragma unroll
            for (int hh = 0; hh < 2; hh++) {
                int t = m0 + am + mi * 16 + er + hh * 8;
                float v0 = fmaxf(acc[mi][nj][hh * 2], 0.f);
                float v1 = fmaxf(acc[mi][nj][hh * 2 + 1], 0.f);
                float ph = (float)t * freq;
                ph = (ph - floorf(ph)) * TWO_PI;
                float sp, cp;
                sincosf(ph, &sp, &cp);
                size_t base = ((size_t)z * Tt + t) * Nn + ne;
                g_xsp[base]     = v0;
                g_xsp[base + 1] = v1;
                g_qr[base]      = rndf(v0 * cp - v1 * sp);
                g_qr[base + 1]  = rndf(v1 * cp + v0 * sp);
            }
        }
}

// ---------------------------------------------------------------------------
// FUSED state+scan: for one (d-tile 128, n-tile 64, z), sweep K=t over 2048
// accumulating sum_t xsT[d][t]*qrT[n][t]; every 4 k-tiles (= chunk 128) dump
// the current accumulator (the EXCLUSIVE prefix) to S[z][j], rounded.
// 8 warps 2(m)x4(n), warp tile 64x16 (NJ=2).
// ---------------------------------------------------------------------------
__global__ __launch_bounds__(256, 2) void k_state_scan()
{
    extern __shared__ float sm[];
    float* As = sm;                             // [3][4608]
    float* Bs = sm + NSTAGE * STAGE_F;          // [3][2304]
    const int tid = threadIdx.x;
    const int lane = tid & 31, warp = tid >> 5;
    const int am = (warp >> 2) * 64, bn = (warp & 3) * 16;
    const int er = lane >> 2, ec = (lane & 3) * 2;
    const int lrowA = (lane & 7) + 8 * ((lane >> 3) & 1);
    const int lcolA = (lane >> 4) * 4;
    const int lrowB = (lane & 7) + 8 * (lane >> 4);
    const int lcolB = ((lane >> 3) & 1) * 4;

    const int ntile = blockIdx.x;    // 0..3 (64-wide n)
    const int dtile = blockIdx.y;    // 0..3 (128-wide d)
    const int z = blockIdx.z;
    const int b = z / NHh;
    const float* A  = g_xsT + ((size_t)b * Dd + dtile * 128) * Tt;  // [d][t]
    const float* Bm = g_qrT + ((size_t)z * Nn + ntile * 64) * Tt;   // [n][t]

    const uint32_t sA0 = (uint32_t)__cvta_generic_to_shared(As);
    const uint32_t sB0 = (uint32_t)__cvta_generic_to_shared(Bs);

    auto load_stage = [&](int st, int k0) {
        float* Ad = As + st * STAGE_F;
        float* Bd = Bs + st * SS_B_STAGE;
        #pragma unroll
        for (int l = 0; l < 4; l++) {
            int c = tid + l * 256;
            int m = c >> 3, seg = (c & 7) << 2;
            cp16((uint32_t)__cvta_generic_to_shared(Ad + m * RS + seg),
                 A + (size_t)m * Tt + k0 + seg);
        }
        #pragma unroll
        for (int l = 0; l < 2; l++) {
            int c = tid + l * 256;
            int n = c >> 3, seg = (c & 7) << 2;
            cp16((uint32_t)__cvta_generic_to_shared(Bd + n * RS + seg),
                 Bm + (size_t)n * Tt + k0 + seg);
        }
    };

    float acc[4][2][4] = {};
    const int nT = Tt / BKT;   // 64
    load_stage(0, 0);
    CP_COMMIT();
    load_stage(1, BKT);
    CP_COMMIT();

    int st = 0;
    for (int t = 0; t < nT; t++) {
        if ((t & 3) == 0) {
            // dump exclusive prefix S[j] (acc = sum of chunks < j)
            int j = t >> 2;
            float* S = g_S + (size_t)(z * NCH + j) * CHSZ;
            #pragma unroll
            for (int mi = 0; mi < 4; mi++)
                #pragma unroll
                for (int nj = 0; nj < 2; nj++) {
                    int d = dtile * 128 + am + mi * 16 + er;
                    int n = ntile * 64 + bn + nj * 8 + ec;
                    S[(size_t)d * Nn + n]           = rndf(acc[mi][nj][0]);
                    S[(size_t)d * Nn + n + 1]       = rndf(acc[mi][nj][1]);
                    S[(size_t)(d + 8) * Nn + n]     = rndf(acc[mi][nj][2]);
                    S[(size_t)(d + 8) * Nn + n + 1] = rndf(acc[mi][nj][3]);
                }
        }
        CP_WAIT1();
        __syncthreads();
        if (t + 2 < nT) {
            int st2 = st + 2 - ((st + 2 >= NSTAGE) ? NSTAGE : 0);
            load_stage(st2, (t + 2) * BKT);
        }
        CP_COMMIT();

        const uint32_t aS = sA0 + st * (STAGE_F * 4);
        const uint32_t bS = sB0 + st * (SS_B_STAGE * 4);
        #pragma unroll
        for (int kg = 0; kg < 4; kg++) {
            const int kk = kg * 8;
            uint32_t a[4][4], bfr[2][2];
            #pragma unroll
            for (int mi = 0; mi < 4; mi++)
                ldsm_x4(a[mi],
                        aS + (uint32_t)(((am + mi * 16 + lrowA) * RS + kk + lcolA) * 4));
            ldsm_x4(&bfr[0][0],
                    bS + (uint32_t)(((bn + lrowB) * RS + kk + lcolB) * 4));
            #pragma unroll
            for (int mi = 0; mi < 4; mi++)
                #pragma unroll
                for (int nj = 0; nj < 2; nj++)
                    asm volatile(
                        "mma.sync.aligned.m16n8k8.row.col.f32.tf32.tf32.f32 "
                        "{%0,%1,%2,%3}, {%4,%5,%6,%7}, {%8,%9}, {%0,%1,%2,%3};"
                        : "+f"(acc[mi][nj][0]), "+f"(acc[mi][nj][1]),
                          "+f"(acc[mi][nj][2]), "+f"(acc[mi][nj][3])
                        : "r"(a[mi][0]), "r"(a[mi][1]), "r"(a[mi][2]), "r"(a[mi][3]),
                          "r"(bfr[nj][0]), "r"(bfr[nj][1]));
        }
        st = (st + 1 == NSTAGE) ? 0 : st + 1;
    }
}

// Intra-chunk masked scores: P[z][i] = (QR_i QR_i^T) ⊙ strict-lower, rounded.
__global__ __launch_bounds__(256, 2) void k_qk_intra()
{
    int zi = blockIdx.x;
    int z = zi / NCH, i = zi % NCH;
    const float* Q = g_qr + ((size_t)z * Tt + (size_t)i * 128) * Nn;
    float acc[4][4][4] = {};
    mma_tile128_nk(Q, Nn, Q, Nn, Nn, acc);
    EPI_SETUP;
    float* P = g_P + (size_t)zi * 128 * 128;
    #pragma unroll
    for (int mi = 0; mi < 4; mi++)
        #pragma unroll
        for (int nj = 0; nj < 4; nj++) {
            int t = am + mi * 16 + er;          // local row
            int s = bn + nj * 8 + ec;           // local col
            P[(size_t)t * 128 + s]           = (t > s)     ? rndf(acc[mi][nj][0]) : 0.f;
            P[(size_t)t * 128 + s + 1]       = (t > s + 1) ? rndf(acc[mi][nj][1]) : 0.f;
            P[(size_t)(t + 8) * 128 + s]     = (t + 8 > s)     ? rndf(acc[mi][nj][2]) : 0.f;
            P[(size_t)(t + 8) * 128 + s + 1] = (t + 8 > s + 1) ? rndf(acc[mi][nj][3]) : 0.f;
        }
}

// yKV chunk: inter (QR_i · S_i, K=256) + intra (P_i · xs_i, K=128).
__global__ __launch_bounds__(256, 2) void k_attn()
{
    int dtile = blockIdx.x;              // 0..3
    int i = blockIdx.y;                  // chunk
    int z = blockIdx.z;
    int b = z / NHh;
    float acc[4][4][4] = {};
    const float* A1 = g_qr + ((size_t)z * Tt + (size_t)i * 128) * Nn;
    const float* B1 = g_S + ((size_t)(z * NCH + i)) * CHSZ + (size_t)(dtile * 128) * Nn;
    mma_tile128_nk(A1, Nn, B1, Nn, Nn, acc);
    __syncthreads();
    const float* A2 = g_P + (size_t)(z * NCH + i) * 128 * 128;
    const float* B2 = g_xsT + ((size_t)b * Dd + dtile * 128) * Tt + i * 128;
    mma_tile128_nk(A2, 128, B2, Tt, 128, acc);
    EPI_SETUP;
    #pragma unroll
    for (int mi = 0; mi < 4; mi++)
        #pragma unroll
        for (int nj = 0; nj < 4; nj++) {
            int t = i * 128 + am + mi * 16 + er;
            int d = dtile * 128 + bn + nj * 8 + ec;
            size_t r0 = ((size_t)z * Tt + t) * Dd;
            size_t r1 = ((size_t)z * Tt + t + 8) * Dd;
            g_ykv[r0 + d]     = acc[mi][nj][0];
            g_ykv[r0 + d + 1] = acc[mi][nj][1];
            g_ykv[r1 + d]     = acc[mi][nj][2];
            g_ykv[r1 + d + 1] = acc[mi][nj][3];
        }
}

// LN of yKV, rounded at write.
__global__ __launch_bounds__(256) void k_ln_ykv()
{
    size_t row = blockIdx.x;
    float* p = g_ykv + row * 512;
    int t = threadIdx.x;
    float o0, o1;
    ln512_pair(p[t], p[t + 256], o0, o1);
    p[t] = rndf(o0);
    p[t + 256] = rndf(o1);
}

// y_sparse = relu(ln(yKV) @ encv[h]); xy = x_sparse * y_sparse -> [b,t,h,n].
__global__ __launch_bounds__(256, 2) void k_venc_mul()
{
    int z = blockIdx.z;
    int b = z / NHh, h = z % NHh;
    int n0 = blockIdx.x * BNT, m0 = blockIdx.y * BMT;
    const float* A  = g_ykv + (size_t)z * Tt * Dd + (size_t)m0 * Dd;
    const float* Bm = g_encvT + ((size_t)h * Nn + n0) * Dd;
    float acc[4][4][4] = {};
    mma_tile128_nk(A, Dd, Bm, Dd, Dd, acc);
    EPI_SETUP;
    #pragma unroll
    for (int mi = 0; mi < 4; mi++)
        #pragma unroll
        for (int nj = 0; nj < 4; nj++) {
            int n = n0 + bn + nj * 8 + ec;
            #pragma unroll
            for (int hh = 0; hh < 2; hh++) {
                int t = m0 + am + mi * 16 + er + hh * 8;
                size_t src = ((size_t)z * Tt + t) * Nn + n;
                size_t dst = (((size_t)(b * Tt + t)) * NHh + h) * Nn + n;
                float y0 = fmaxf(acc[mi][nj][hh * 2], 0.f);
                float y1 = fmaxf(acc[mi][nj][hh * 2 + 1], 0.f);
                g_xy[dst]     = rndf(y0 * g_xsp[src]);
                g_xy[dst + 1] = rndf(y1 * g_xsp[src + 1]);
            }
        }
}

// yMLP = xy[4096,2048] @ decoder[2048,512]; B = decT [d][hn].
__global__ __launch_bounds__(256, 2) void k_dec()
{
    int n0 = blockIdx.x * BNT, m0 = blockIdx.y * BMT;
    float acc[4][4][4] = {};
    mma_tile128_nk(g_xy + (size_t)m0 * HN, HN, g_decT + (size_t)n0 * HN, HN, HN, acc);
    EPI_SETUP;
    #pragma unroll
    for (int mi = 0; mi < 4; mi++)
        #pragma unroll
        for (int nj = 0; nj < 4; nj++) {
            int m = m0 + am + mi * 16 + er;
            int n = n0 + bn + nj * 8 + ec;
            g_tmp[(size_t)m * Dd + n]           = acc[mi][nj][0];
            g_tmp[(size_t)m * Dd + n + 1]       = acc[mi][nj][1];
            g_tmp[(size_t)(m + 8) * Dd + n]     = acc[mi][nj][2];
            g_tmp[(size_t)(m + 8) * Dd + n + 1] = acc[mi][nj][3];
        }
}

__global__ __launch_bounds__(256) void k_resid_ln()
{
    size_t row = blockIdx.x;
    const float* a = g_xs + row * 512;
    const float* bp = g_tmp + row * 512;
    int t = threadIdx.x;
    float l0, l1;
    ln512_pair(bp[t], bp[t + 256], l0, l1);
    float t0 = a[t] + l0, t1 = a[t + 256] + l1;
    float o0, o1;
    ln512_pair(t0, t1, o0, o1);
    g_xs[row * 512 + t] = o0;
    g_xs[row * 512 + t + 256] = o1;
    g_xs_r[row * 512 + t] = rndf(o0);
    g_xs_r[row * 512 + t + 256] = rndf(o1);
}

__global__ __launch_bounds__(256, 2) void k_head(
    const float* __restrict__ hb, float* __restrict__ out)
{
    int n0 = blockIdx.x * BNT, m0 = blockIdx.y * BMT;
    float acc[4][4][4] = {};
    mma_tile128_nk(g_xs_r + (size_t)m0 * Dd, Dd, g_hwT + (size_t)n0 * Dd, Dd, Dd, acc);
    EPI_SETUP;
    #pragma unroll
    for (int mi = 0; mi < 4; mi++)
        #pragma unroll
        for (int nj = 0; nj < 4; nj++) {
            int m = m0 + am + mi * 16 + er;
            int n = n0 + bn + nj * 8 + ec;
            out[(size_t)m * Dd + n]           = acc[mi][nj][0] + hb[n];
            out[(size_t)m * Dd + n + 1]       = acc[mi][nj][1] + hb[n + 1];
            out[(size_t)(m + 8) * Dd + n]     = acc[mi][nj][2] + hb[n];
            out[(size_t)(m + 8) * Dd + n + 1] = acc[mi][nj][3] + hb[n + 1];
        }
}

// ---------------------------------------------------------------------------
extern "C" void kernel_launch(void* const* d_in, const int* in_sizes, int n_in,
                              void* d_out, int out_size)
{
    const float* x    = (const float*)d_in[0];
    const float* w_in = (const float*)d_in[1];
    const float* b_in = (const float*)d_in[2];
    const float* enc  = (const float*)d_in[3];
    const float* encv = (const float*)d_in[4];
    const float* dec  = (const float*)d_in[5];
    const float* hw   = (const float*)d_in[6];
    const float* hb   = (const float*)d_in[7];
    float* out = (float*)d_out;

    static bool attr_done = false;
    if (!attr_done) {
        cudaFuncSetAttribute(k_inproj,     cudaFuncAttributeMaxDynamicSharedMemorySize, SMEM_BYTES);
        cudaFuncSetAttribute(k_enc_rope,   cudaFuncAttributeMaxDynamicSharedMemorySize, SMEM_BYTES);
        cudaFuncSetAttribute(k_state_scan, cudaFuncAttributeMaxDynamicSharedMemorySize, SMEM_SS);
        cudaFuncSetAttribute(k_qk_intra,   cudaFuncAttributeMaxDynamicSharedMemorySize, SMEM_BYTES);
        cudaFuncSetAttribute(k_attn,       cudaFuncAttributeMaxDynamicSharedMemorySize, SMEM_BYTES);
        cudaFuncSetAttribute(k_venc_mul,   cudaFuncAttributeMaxDynamicSharedMemorySize, SMEM_BYTES);
        cudaFuncSetAttribute(k_dec,        cudaFuncAttributeMaxDynamicSharedMemorySize, SMEM_BYTES);
        cudaFuncSetAttribute(k_head,       cudaFuncAttributeMaxDynamicSharedMemorySize, SMEM_BYTES);
        attr_done = true;
    }

    dim3 blk(256);

    k_prep<<<512, 256>>>(x, w_in, enc, encv, dec, hw);

    k_inproj<<<dim3(Dd / BNT, BT / BMT), blk, SMEM_BYTES>>>(b_in);
    k_ln_inproj<<<BT, 256>>>();

    for (int layer = 0; layer < 3; layer++) {
        k_enc_rope<<<dim3(Nn / BNT, Tt / BMT, BH), blk, SMEM_BYTES>>>();
        k_tr_xs<<<dim3(Tt / 32, Dd / 32, Bb), 256>>>();
        k_tr_qr<<<dim3(Tt / 32, Nn / 32, BH), 256>>>();
        k_state_scan<<<dim3(4, 4, BH), blk, SMEM_SS>>>();
        k_qk_intra<<<dim3(BH * NCH), blk, SMEM_BYTES>>>();
        k_attn<<<dim3(Dd / BNT, NCH, BH), blk, SMEM_BYTES>>>();
        k_ln_ykv<<<BH * Tt, 256>>>();
        k_venc_mul<<<dim3(Nn / BNT, Tt / BMT, BH), blk, SMEM_BYTES>>>();
        k_dec<<<dim3(Dd / BNT, BT / BMT), blk, SMEM_BYTES>>>();
        k_resid_ln<<<BT, 256>>>();
    }

    k_head<<<dim3(Dd / BNT, BT / BMT), blk, SMEM_BYTES>>>(hb, out);
}